// round 11
// baseline (speedup 1.0000x reference)
#include <cuda_runtime.h>

#define TILE_W 64
#define TILE_H 64
#define HALO 5
#define R_ROWS (TILE_H + 2*HALO)   // 74
#define R_COLS (TILE_W + 2*HALO)   // 74
#define NTHREADS 512
#define IMG 512
#define PLANES 48
#define GRID_X (IMG / TILE_W)      // 8
#define GRID_Y (IMG / TILE_H)      // 8
#define NBLOCKS (GRID_X * GRID_Y * PLANES)  // 3072

#define C1v 0.0001f
#define C2v 0.0009f

// Union row-block layout, ROWSTRIDE=326 words (1304 B, 8B-aligned rows):
//   input (live until h write):  float2 (p,t) pairs at words [2c], c=0..74
//   h-planes (overwrite):        A=(mp,mt) pairs at [2c]      c=0..63
//                                B=(pp,tt) pairs at [128+2c]
//                                C= pt     scalar at [256+c]
// 74 * 326 = 24124 floats = 96496 B per CTA -> 2 CTAs/SM (32 warps, same occ).
#define ROWSTRIDE 326
#define SMEM_BYTES (R_ROWS * ROWSTRIDE * 4)

// Gaussian(sigma=1.5, k=11); symmetric: 6 distinct values.
__device__ constexpr float Wc[11] = {
    0.00102838f, 0.00759876f, 0.03600077f, 0.10936070f, 0.21300553f,
    0.26601172f, 0.21300553f, 0.10936070f, 0.03600077f, 0.00759876f,
    0.00102838f
};

typedef unsigned long long u64;

__device__ __forceinline__ u64 pk2(float lo, float hi) {
    u64 r; asm("mov.b64 %0, {%1, %2};" : "=l"(r) : "f"(lo), "f"(hi)); return r;
}
__device__ __forceinline__ void upk2(float& lo, float& hi, u64 v) {
    asm("mov.b64 {%0, %1}, %2;" : "=f"(lo), "=f"(hi) : "l"(v));
}
__device__ __forceinline__ u64 fma2(u64 a, u64 b, u64 c) {
    u64 d; asm("fma.rn.f32x2 %0, %1, %2, %3;" : "=l"(d) : "l"(a), "l"(b), "l"(c)); return d;
}
__device__ __forceinline__ u64 mul2(u64 a, u64 b) {
    u64 d; asm("mul.rn.f32x2 %0, %1, %2;" : "=l"(d) : "l"(a), "l"(b)); return d;
}

__device__ double g_accum = 0.0;
__device__ unsigned int g_count = 0u;

// Horizontal blur: W-wide column group at (r, c0). Packed (p,t),(pp,tt), scalar pt.
template<int W>
__device__ __forceinline__ void hblur_row(const float* __restrict__ s, const u64* ww,
                                          int r, int c0,
                                          u64* am, u64* as_, float* apt) {
    #pragma unroll
    for (int o = 0; o < W; ++o) { am[o] = 0ull; as_[o] = 0ull; apt[o] = 0.f; }
    const float* rowbase = s + r * ROWSTRIDE;
    #pragma unroll
    for (int k = 0; k < W + 10; ++k) {
        u64 v = *(const u64*)(rowbase + 2 * (c0 + k));   // (p,t) pair, LDS.64
        u64 sq = mul2(v, v);                             // (pp,tt)
        float a, b; upk2(a, b, v);
        float ab = a * b;
        #pragma unroll
        for (int o = 0; o < W; ++o) {
            int tp = k - o;                              // compile-time
            if (tp >= 0 && tp < 11) {
                int wi = (tp <= 5) ? tp : 10 - tp;
                am[o]  = fma2(v,  ww[wi], am[o]);
                as_[o] = fma2(sq, ww[wi], as_[o]);
                apt[o] = fmaf(Wc[tp], ab, apt[o]);       // FFMA-imm
            }
        }
    }
}

template<int W>
__device__ __forceinline__ void hblur_store(float* __restrict__ s, int r, int c0,
                                            const u64* am, const u64* as_, const float* apt) {
    float* rb = s + r * ROWSTRIDE;
    #pragma unroll
    for (int o = 0; o < W; ++o) {
        *(u64*)(rb + 2 * (c0 + o))       = am[o];        // A plane
        *(u64*)(rb + 128 + 2 * (c0 + o)) = as_[o];       // B plane
        rb[256 + c0 + o] = apt[o];                       // C plane
    }
}

__global__ __launch_bounds__(NTHREADS, 2)   // 64 regs, 2 CTAs/SM (smem-bound)
void ssim_kernel(const float* __restrict__ pred, const float* __restrict__ targ,
                 float* __restrict__ out) {
    extern __shared__ float s[];
    __shared__ float red[NTHREADS / 32];

    const int tid = threadIdx.x;
    const int x0 = blockIdx.x * TILE_W;
    const int y0 = blockIdx.y * TILE_H;
    const long long plane_off = (long long)blockIdx.z * (IMG * IMG);
    const float* p = pred + plane_off;
    const float* t = targ + plane_off;

    // packed symmetric weights (6 reg pairs; thread-invariant)
    u64 ww[6];
    #pragma unroll
    for (int i = 0; i < 6; ++i) ww[i] = pk2(Wc[i], Wc[i]);

    // ---- Phase 1: load halo tile, (x+1)/2; OOB = 0 (zero pad) ----
    // Unrolled, predicated iterations: front-batched LDGs -> high MLP.
    #pragma unroll
    for (int i = 0; i < 11; ++i) {
        int idx = tid + i * NTHREADS;
        if (idx < R_ROWS * R_COLS) {
            int r = idx / R_COLS;
            int c = idx - r * R_COLS;
            int gy = y0 - HALO + r;
            int gx = x0 - HALO + c;
            float a = 0.0f, b = 0.0f;
            if ((unsigned)gy < IMG && (unsigned)gx < IMG) {
                int g = gy * IMG + gx;
                a = fmaf(0.5f, p[g], 0.5f);
                b = fmaf(0.5f, t[g], 0.5f);
            }
            *(float2*)(s + r * ROWSTRIDE + 2 * c) = make_float2(a, b);
        }
    }
    __syncthreads();

    // ---- Round 1: h-blur rows 0..63, 8-wide (512 units, one per thread) ----
    u64 am[8], as_[8]; float apt[8];
    const int r1 = tid & 63;             // lanes span rows (stride 326 -> conflict-free)
    const int c1 = (tid >> 6) << 3;
    hblur_row<8>(s, ww, r1, c1, am, as_, apt);
    __syncthreads();

    // ---- Round 1 write-back + Round 2 compute rows 64..73, 4-wide ----
    // 10 rows x 16 groups = 160 units -> half-length critical path.
    hblur_store<8>(s, r1, c1, am, as_, apt);
    const int r2 = 64 + (tid % 10);
    const int c2 = (tid / 10) << 2;
    if (tid < 160)
        hblur_row<4>(s, ww, r2, c2, am, as_, apt);
    __syncthreads();

    if (tid < 160)
        hblur_store<4>(s, r2, c2, am, as_, apt);
    __syncthreads();

    // ---- Phase 3: vertical blur (8-tall window) + SSIM; all 512 threads ----
    const int c  = tid & (TILE_W - 1);
    const int r0 = (tid >> 6) << 3;      // 0,8,...,56
    u64 vm[8], vs_[8]; float vpt[8];
    #pragma unroll
    for (int o = 0; o < 8; ++o) { vm[o] = 0ull; vs_[o] = 0ull; vpt[o] = 0.f; }
    #pragma unroll
    for (int k = 0; k < 18; ++k) {
        const float* rb = s + (r0 + k) * ROWSTRIDE;
        u64  hm  = *(const u64*)(rb + 2 * c);            // (mp,mt)
        u64  hs  = *(const u64*)(rb + 128 + 2 * c);      // (pp,tt)
        float hpt = rb[256 + c];
        #pragma unroll
        for (int o = 0; o < 8; ++o) {
            int tp = k - o;
            if (tp >= 0 && tp < 11) {
                int wi = (tp <= 5) ? tp : 10 - tp;
                vm[o]  = fma2(hm, ww[wi], vm[o]);
                vs_[o] = fma2(hs, ww[wi], vs_[o]);
                vpt[o] = fmaf(Wc[tp], hpt, vpt[o]);
            }
        }
    }

    float local = 0.0f;
    #pragma unroll
    for (int o = 0; o < 8; ++o) {
        float mu_p, mu_t, epp, ett;
        upk2(mu_p, mu_t, vm[o]);
        upk2(epp, ett, vs_[o]);
        float mpp = mu_p * mu_p;
        float mtt = mu_t * mu_t;
        float mpt = mu_p * mu_t;
        float sp  = epp - mpp;
        float st_ = ett - mtt;
        float spt = vpt[o] - mpt;
        float num = (2.0f * mpt + C1v) * (2.0f * spt + C2v);
        float den = (mpp + mtt + C1v) * (sp + st_ + C2v);
        local += __fdividef(num, den);
    }

    // ---- Block reduction -> device accumulator; last block finalizes ----
    #pragma unroll
    for (int sh = 16; sh > 0; sh >>= 1)
        local += __shfl_down_sync(0xffffffffu, local, sh);
    if ((tid & 31) == 0) red[tid >> 5] = local;
    __syncthreads();
    if (tid < 32) {
        float v = (tid < (NTHREADS / 32)) ? red[tid] : 0.0f;
        #pragma unroll
        for (int sh = 8; sh > 0; sh >>= 1)
            v += __shfl_down_sync(0xffffffffu, v, sh);
        if (tid == 0) {
            atomicAdd(&g_accum, (double)v);
            __threadfence();
            unsigned prev = atomicAdd(&g_count, 1u);
            if (prev == (unsigned)(NBLOCKS - 1)) {
                double tot = atomicAdd(&g_accum, 0.0);
                const double N = (double)PLANES * (double)(IMG * IMG);
                out[0] = (float)(1.0 - tot / N);
                g_accum = 0.0;
                g_count = 0u;
            }
        }
    }
}

extern "C" void kernel_launch(void* const* d_in, const int* in_sizes, int n_in,
                              void* d_out, int out_size) {
    const float* pred = (const float*)d_in[0];
    const float* targ = (const float*)d_in[1];

    cudaFuncSetAttribute(ssim_kernel, cudaFuncAttributeMaxDynamicSharedMemorySize, SMEM_BYTES);

    dim3 grid(GRID_X, GRID_Y, PLANES);
    ssim_kernel<<<grid, NTHREADS, SMEM_BYTES>>>(pred, targ, (float*)d_out);
}

// round 16
// speedup vs baseline: 1.0095x; 1.0095x over previous
#include <cuda_runtime.h>

#define TILE_W 64
#define TILE_H 64
#define HALO 5
#define R_ROWS (TILE_H + 2*HALO)   // 74
#define R_COLS (TILE_W + 2*HALO)   // 74
#define NTHREADS 512
#define IMG 512
#define PLANES 48
#define GRID_X (IMG / TILE_W)      // 8
#define GRID_Y (IMG / TILE_H)      // 8
#define NBLOCKS (GRID_X * GRID_Y * PLANES)  // 3072

#define C1v 0.0001f
#define C2v 0.0009f

// Union row-block layout, ROWSTRIDE=326 words (1304 B, 8B-aligned rows):
//   input (live until h write):  float2 (p,t) pairs at words [2c], c=0..74
//   h-planes (overwrite):        A=(mp,mt) pairs at [2c]      c=0..63
//                                B=(pp,tt) pairs at [128+2c]
//                                C= pt     scalar at [256+c]
// 74 * 326 = 24124 floats = 96496 B per CTA -> 2 CTAs/SM (32 warps).
#define ROWSTRIDE 326
#define SMEM_BYTES (R_ROWS * ROWSTRIDE * 4)

// Gaussian(sigma=1.5, k=11); symmetric: 6 distinct values.
__device__ constexpr float Wc[11] = {
    0.00102838f, 0.00759876f, 0.03600077f, 0.10936070f, 0.21300553f,
    0.26601172f, 0.21300553f, 0.10936070f, 0.03600077f, 0.00759876f,
    0.00102838f
};

typedef unsigned long long u64;

__device__ __forceinline__ u64 pk2(float lo, float hi) {
    u64 r; asm("mov.b64 %0, {%1, %2};" : "=l"(r) : "f"(lo), "f"(hi)); return r;
}
__device__ __forceinline__ void upk2(float& lo, float& hi, u64 v) {
    asm("mov.b64 {%0, %1}, %2;" : "=f"(lo), "=f"(hi) : "l"(v));
}
__device__ __forceinline__ u64 fma2(u64 a, u64 b, u64 c) {
    u64 d; asm("fma.rn.f32x2 %0, %1, %2, %3;" : "=l"(d) : "l"(a), "l"(b), "l"(c)); return d;
}
__device__ __forceinline__ u64 mul2(u64 a, u64 b) {
    u64 d; asm("mul.rn.f32x2 %0, %1, %2;" : "=l"(d) : "l"(a), "l"(b)); return d;
}

__device__ double g_accum = 0.0;
__device__ unsigned int g_count = 0u;

// Horizontal blur: W-wide column group at (r, c0). Packed (p,t),(pp,tt), scalar pt.
template<int W>
__device__ __forceinline__ void hblur_row(const float* __restrict__ s, const u64* ww,
                                          int r, int c0,
                                          u64* am, u64* as_, float* apt) {
    #pragma unroll
    for (int o = 0; o < W; ++o) { am[o] = 0ull; as_[o] = 0ull; apt[o] = 0.f; }
    const float* rowbase = s + r * ROWSTRIDE;
    #pragma unroll
    for (int k = 0; k < W + 10; ++k) {
        u64 v = *(const u64*)(rowbase + 2 * (c0 + k));   // (p,t) pair, LDS.64
        u64 sq = mul2(v, v);                             // (pp,tt)
        float a, b; upk2(a, b, v);
        float ab = a * b;
        #pragma unroll
        for (int o = 0; o < W; ++o) {
            int tp = k - o;                              // compile-time
            if (tp >= 0 && tp < 11) {
                int wi = (tp <= 5) ? tp : 10 - tp;
                am[o]  = fma2(v,  ww[wi], am[o]);
                as_[o] = fma2(sq, ww[wi], as_[o]);
                apt[o] = fmaf(Wc[tp], ab, apt[o]);       // FFMA-imm
            }
        }
    }
}

template<int W>
__device__ __forceinline__ void hblur_store(float* __restrict__ s, int r, int c0,
                                            const u64* am, const u64* as_, const float* apt) {
    float* rb = s + r * ROWSTRIDE;
    #pragma unroll
    for (int o = 0; o < W; ++o) {
        *(u64*)(rb + 2 * (c0 + o))       = am[o];        // A plane
        *(u64*)(rb + 128 + 2 * (c0 + o)) = as_[o];       // B plane
        rb[256 + c0 + o] = apt[o];                       // C plane
    }
}

__global__ __launch_bounds__(NTHREADS, 2)   // 64 regs, 2 CTAs/SM (smem-bound)
void ssim_kernel(const float* __restrict__ pred, const float* __restrict__ targ,
                 float* __restrict__ out) {
    extern __shared__ float s[];
    __shared__ float red[NTHREADS / 32];

    const int tid = threadIdx.x;
    const int x0 = blockIdx.x * TILE_W;
    const int y0 = blockIdx.y * TILE_H;
    const long long plane_off = (long long)blockIdx.z * (IMG * IMG);
    const float* p = pred + plane_off;
    const float* t = targ + plane_off;

    // packed symmetric weights (6 reg pairs; thread-invariant)
    u64 ww[6];
    #pragma unroll
    for (int i = 0; i < 6; ++i) ww[i] = pk2(Wc[i], Wc[i]);

    // ---- Phase 1: load halo tile, (x+1)/2; OOB = 0 (zero pad) ----
    // One div/mod, then incremental (r,c); unrolled -> front-batched LDGs.
    {
        int r = tid / R_COLS;            // 0..7
        int c = tid - r * R_COLS;
        #pragma unroll
        for (int i = 0; i < 11; ++i) {
            if (i * NTHREADS + tid < R_ROWS * R_COLS) {
                int gy = y0 - HALO + r;
                int gx = x0 - HALO + c;
                float a = 0.0f, b = 0.0f;
                if ((unsigned)gy < IMG && (unsigned)gx < IMG) {
                    int g = gy * IMG + gx;
                    a = fmaf(0.5f, p[g], 0.5f);
                    b = fmaf(0.5f, t[g], 0.5f);
                }
                *(float2*)(s + r * ROWSTRIDE + 2 * c) = make_float2(a, b);
            }
            c += NTHREADS - 6 * R_COLS;  // +68
            r += 6;
            if (c >= R_COLS) { c -= R_COLS; ++r; }
        }
    }
    __syncthreads();

    // ---- Round 1: h-blur rows 0..63, 8-wide (512 units, one per thread) ----
    u64 am[8], as_[8]; float apt[8];
    const int r1 = tid & 63;             // lanes span rows (stride 326 -> conflict-free)
    const int c1 = (tid >> 6) << 3;
    hblur_row<8>(s, ww, r1, c1, am, as_, apt);
    __syncthreads();

    // ---- Round 1 write-back + Round 2 compute rows 64..73, 2-wide ----
    // 10 rows x 32 groups = 320 units, c-fast: short critical path, cheap idx,
    // consecutive-column LDS.64 -> conflict-free.
    hblur_store<8>(s, r1, c1, am, as_, apt);
    const int r2 = 64 + (tid >> 5);
    const int c2 = (tid & 31) << 1;
    if (tid < 320)
        hblur_row<2>(s, ww, r2, c2, am, as_, apt);
    __syncthreads();

    if (tid < 320)
        hblur_store<2>(s, r2, c2, am, as_, apt);
    __syncthreads();

    // ---- Phase 3: vertical blur (8-tall window) + SSIM; all 512 threads ----
    const int c  = tid & (TILE_W - 1);
    const int r0 = (tid >> 6) << 3;      // 0,8,...,56
    u64 vm[8], vs_[8]; float vpt[8];
    #pragma unroll
    for (int o = 0; o < 8; ++o) { vm[o] = 0ull; vs_[o] = 0ull; vpt[o] = 0.f; }
    #pragma unroll
    for (int k = 0; k < 18; ++k) {
        const float* rb = s + (r0 + k) * ROWSTRIDE;
        u64  hm  = *(const u64*)(rb + 2 * c);            // (mp,mt)
        u64  hs  = *(const u64*)(rb + 128 + 2 * c);      // (pp,tt)
        float hpt = rb[256 + c];
        #pragma unroll
        for (int o = 0; o < 8; ++o) {
            int tp = k - o;
            if (tp >= 0 && tp < 11) {
                int wi = (tp <= 5) ? tp : 10 - tp;
                vm[o]  = fma2(hm, ww[wi], vm[o]);
                vs_[o] = fma2(hs, ww[wi], vs_[o]);
                vpt[o] = fmaf(Wc[tp], hpt, vpt[o]);
            }
        }
    }

    float local = 0.0f;
    #pragma unroll
    for (int o = 0; o < 8; ++o) {
        float mu_p, mu_t, epp, ett;
        upk2(mu_p, mu_t, vm[o]);
        upk2(epp, ett, vs_[o]);
        float mpp = mu_p * mu_p;
        float mtt = mu_t * mu_t;
        float mpt = mu_p * mu_t;
        float sp  = epp - mpp;
        float st_ = ett - mtt;
        float spt = vpt[o] - mpt;
        float num = (2.0f * mpt + C1v) * (2.0f * spt + C2v);
        float den = (mpp + mtt + C1v) * (sp + st_ + C2v);
        local += __fdividef(num, den);
    }

    // ---- Block reduction -> device accumulator; last block finalizes ----
    #pragma unroll
    for (int sh = 16; sh > 0; sh >>= 1)
        local += __shfl_down_sync(0xffffffffu, local, sh);
    if ((tid & 31) == 0) red[tid >> 5] = local;
    __syncthreads();
    if (tid < 32) {
        float v = (tid < (NTHREADS / 32)) ? red[tid] : 0.0f;
        #pragma unroll
        for (int sh = 8; sh > 0; sh >>= 1)
            v += __shfl_down_sync(0xffffffffu, v, sh);
        if (tid == 0) {
            atomicAdd(&g_accum, (double)v);
            __threadfence();
            unsigned prev = atomicAdd(&g_count, 1u);
            if (prev == (unsigned)(NBLOCKS - 1)) {
                double tot = atomicAdd(&g_accum, 0.0);
                const double N = (double)PLANES * (double)(IMG * IMG);
                out[0] = (float)(1.0 - tot / N);
                g_accum = 0.0;
                g_count = 0u;
            }
        }
    }
}

extern "C" void kernel_launch(void* const* d_in, const int* in_sizes, int n_in,
                              void* d_out, int out_size) {
    const float* pred = (const float*)d_in[0];
    const float* targ = (const float*)d_in[1];

    cudaFuncSetAttribute(ssim_kernel, cudaFuncAttributeMaxDynamicSharedMemorySize, SMEM_BYTES);

    dim3 grid(GRID_X, GRID_Y, PLANES);
    ssim_kernel<<<grid, NTHREADS, SMEM_BYTES>>>(pred, targ, (float*)d_out);
}

// round 17
// speedup vs baseline: 1.1577x; 1.1468x over previous
#include <cuda_runtime.h>

#define TILE_W 64
#define TILE_H 32
#define HALO 5
#define R_ROWS (TILE_H + 2*HALO)   // 42
#define R_COLS (TILE_W + 2*HALO)   // 74
#define NTHREADS 256
#define IMG 512
#define PLANES 48
#define GRID_X (IMG / TILE_W)      // 8
#define GRID_Y (IMG / TILE_H)      // 16
#define NBLOCKS (GRID_X * GRID_Y * PLANES)  // 6144

#define C1v 0.0001f
#define C2v 0.0009f

// Union row-block layout, ROWSTRIDE=258 words (1032 B, 8B-aligned rows):
//   input (live until h write):  float2 (p,t) pairs at words [2c], c=0..74  -> [0..149]
//   h-planes (overwrite):        A=(mu_p,mu_t) pairs at [2c]       c=0..63 -> [0..127]
//                                B=(q, pt) pairs at [128+2c]       c=0..63 -> [128..255]
//   where q = p^2+t^2 blurred, pt = p*t blurred. Only 4 fields needed:
//   sigma_p^2+sigma_t^2 = E[p^2+t^2] - (mu_p^2+mu_t^2).
// 42 * 258 * 4 = 43344 B per CTA -> 5 CTAs/SM (216.7 KB), 40 warps/SM.
// Stride 258 == 2 (mod 32): LDS.64 r-fast covers all 32 banks, conflict-free.
#define ROWSTRIDE 258
#define SMEM_BYTES (R_ROWS * ROWSTRIDE * 4)

// Gaussian(sigma=1.5, k=11); symmetric: 6 distinct values.
__device__ constexpr float Wc[11] = {
    0.00102838f, 0.00759876f, 0.03600077f, 0.10936070f, 0.21300553f,
    0.26601172f, 0.21300553f, 0.10936070f, 0.03600077f, 0.00759876f,
    0.00102838f
};

typedef unsigned long long u64;

__device__ __forceinline__ u64 pk2(float lo, float hi) {
    u64 r; asm("mov.b64 %0, {%1, %2};" : "=l"(r) : "f"(lo), "f"(hi)); return r;
}
__device__ __forceinline__ void upk2(float& lo, float& hi, u64 v) {
    asm("mov.b64 {%0, %1}, %2;" : "=f"(lo), "=f"(hi) : "l"(v));
}
__device__ __forceinline__ u64 fma2(u64 a, u64 b, u64 c) {
    u64 d; asm("fma.rn.f32x2 %0, %1, %2, %3;" : "=l"(d) : "l"(a), "l"(b), "l"(c)); return d;
}

__device__ double g_accum = 0.0;
__device__ unsigned int g_count = 0u;

// Horizontal blur, W-wide group at (r, c0): two packed fields (p,t) and (q,pt).
template<int W>
__device__ __forceinline__ void hblur_row(const float* __restrict__ s, const u64* ww,
                                          int r, int c0, u64* am, u64* aq) {
    #pragma unroll
    for (int o = 0; o < W; ++o) { am[o] = 0ull; aq[o] = 0ull; }
    const float* rowbase = s + r * ROWSTRIDE;
    #pragma unroll
    for (int k = 0; k < W + 10; ++k) {
        u64 v = *(const u64*)(rowbase + 2 * (c0 + k));   // (p,t), LDS.64
        float a, b; upk2(a, b, v);
        float q  = fmaf(a, a, b * b);                    // p^2+t^2
        float ab = a * b;                                // p*t
        u64 u = pk2(q, ab);
        #pragma unroll
        for (int o = 0; o < W; ++o) {
            int tp = k - o;                              // compile-time
            if (tp >= 0 && tp < 11) {
                int wi = (tp <= 5) ? tp : 10 - tp;
                am[o] = fma2(v, ww[wi], am[o]);
                aq[o] = fma2(u, ww[wi], aq[o]);
            }
        }
    }
}

template<int W>
__device__ __forceinline__ void hblur_store(float* __restrict__ s, int r, int c0,
                                            const u64* am, const u64* aq) {
    float* rb = s + r * ROWSTRIDE;
    #pragma unroll
    for (int o = 0; o < W; ++o) {
        *(u64*)(rb + 2 * (c0 + o))       = am[o];        // A plane (mu_p,mu_t)
        *(u64*)(rb + 128 + 2 * (c0 + o)) = aq[o];        // B plane (q,pt)
    }
}

__global__ __launch_bounds__(NTHREADS, 5)   // cap 51 regs -> 5 CTAs/SM
void ssim_kernel(const float* __restrict__ pred, const float* __restrict__ targ,
                 float* __restrict__ out) {
    extern __shared__ float s[];
    __shared__ float red[NTHREADS / 32];

    const int tid = threadIdx.x;
    const int x0 = blockIdx.x * TILE_W;
    const int y0 = blockIdx.y * TILE_H;
    const long long plane_off = (long long)blockIdx.z * (IMG * IMG);
    const float* p = pred + plane_off;
    const float* t = targ + plane_off;

    // packed symmetric weights (6 reg pairs; thread-invariant)
    u64 ww[6];
    #pragma unroll
    for (int i = 0; i < 6; ++i) ww[i] = pk2(Wc[i], Wc[i]);

    // ---- Phase 1: load halo tile, (x+1)/2; OOB = 0 (zero pad) ----
    // One div/mod, then incremental (r,c); unrolled -> front-batched LDGs.
    {
        int r = tid / R_COLS;
        int c = tid - r * R_COLS;
        #pragma unroll
        for (int i = 0; i < 13; ++i) {
            if (i * NTHREADS + tid < R_ROWS * R_COLS) {
                int gy = y0 - HALO + r;
                int gx = x0 - HALO + c;
                float a = 0.0f, b = 0.0f;
                if ((unsigned)gy < IMG && (unsigned)gx < IMG) {
                    int g = gy * IMG + gx;
                    a = fmaf(0.5f, p[g], 0.5f);
                    b = fmaf(0.5f, t[g], 0.5f);
                }
                *(float2*)(s + r * ROWSTRIDE + 2 * c) = make_float2(a, b);
            }
            c += NTHREADS - 3 * R_COLS;  // +34
            r += 3;
            if (c >= R_COLS) { c -= R_COLS; ++r; }
        }
    }
    __syncthreads();

    // ---- Round 1: h-blur rows 0..31, 8-wide (256 units, one per thread) ----
    u64 am[8], aq[8];
    const int r1 = tid & 31;             // lanes span rows (stride 258 -> conflict-free)
    const int c1 = (tid >> 5) << 3;
    hblur_row<8>(s, ww, r1, c1, am, aq);
    __syncthreads();

    // ---- Round 1 write-back + Round 2: rows 32..41, 4-wide (160 units) ----
    hblur_store<8>(s, r1, c1, am, aq);
    const int r2 = 32 + (tid % 10);
    const int c2 = (tid / 10) << 2;
    if (tid < 160)
        hblur_row<4>(s, ww, r2, c2, am, aq);
    __syncthreads();

    if (tid < 160)
        hblur_store<4>(s, r2, c2, am, aq);
    __syncthreads();

    // ---- Phase 3: vertical blur (8-tall window) + SSIM; all 256 threads ----
    const int c  = tid & (TILE_W - 1);
    const int r0 = (tid >> 6) << 3;      // 0,8,16,24
    u64 vm[8], vq[8];
    #pragma unroll
    for (int o = 0; o < 8; ++o) { vm[o] = 0ull; vq[o] = 0ull; }
    #pragma unroll
    for (int k = 0; k < 18; ++k) {
        const float* rb = s + (r0 + k) * ROWSTRIDE;
        u64 hm = *(const u64*)(rb + 2 * c);              // (mu_p,mu_t)
        u64 hq = *(const u64*)(rb + 128 + 2 * c);        // (q,pt)
        #pragma unroll
        for (int o = 0; o < 8; ++o) {
            int tp = k - o;
            if (tp >= 0 && tp < 11) {
                int wi = (tp <= 5) ? tp : 10 - tp;
                vm[o] = fma2(hm, ww[wi], vm[o]);
                vq[o] = fma2(hq, ww[wi], vq[o]);
            }
        }
    }

    float local = 0.0f;
    #pragma unroll
    for (int o = 0; o < 8; ++o) {
        float mu_p, mu_t, qe, pte;
        upk2(mu_p, mu_t, vm[o]);
        upk2(qe, pte, vq[o]);
        float mpt = mu_p * mu_t;                     // mu_p*mu_t
        float m2  = fmaf(mu_p, mu_p, mu_t * mu_t);   // mu_p^2+mu_t^2
        float spt  = pte - mpt;                      // sigma_pt
        float sden = qe - m2 + C2v;                  // sigma_p^2+sigma_t^2+C2
        float num = (2.0f * mpt + C1v) * (2.0f * spt + C2v);
        float den = (m2 + C1v) * sden;
        local += __fdividef(num, den);
    }

    // ---- Block reduction -> device accumulator; last block finalizes ----
    #pragma unroll
    for (int sh = 16; sh > 0; sh >>= 1)
        local += __shfl_down_sync(0xffffffffu, local, sh);
    if ((tid & 31) == 0) red[tid >> 5] = local;
    __syncthreads();
    if (tid < 32) {
        float v = (tid < (NTHREADS / 32)) ? red[tid] : 0.0f;
        #pragma unroll
        for (int sh = 4; sh > 0; sh >>= 1)
            v += __shfl_down_sync(0xffffffffu, v, sh);
        if (tid == 0) {
            atomicAdd(&g_accum, (double)v);
            __threadfence();
            unsigned prev = atomicAdd(&g_count, 1u);
            if (prev == (unsigned)(NBLOCKS - 1)) {
                double tot = atomicAdd(&g_accum, 0.0);
                const double N = (double)PLANES * (double)(IMG * IMG);
                out[0] = (float)(1.0 - tot / N);
                g_accum = 0.0;
                g_count = 0u;
            }
        }
    }
}

extern "C" void kernel_launch(void* const* d_in, const int* in_sizes, int n_in,
                              void* d_out, int out_size) {
    const float* pred = (const float*)d_in[0];
    const float* targ = (const float*)d_in[1];

    cudaFuncSetAttribute(ssim_kernel, cudaFuncAttributeMaxDynamicSharedMemorySize, SMEM_BYTES);

    dim3 grid(GRID_X, GRID_Y, PLANES);
    ssim_kernel<<<grid, NTHREADS, SMEM_BYTES>>>(pred, targ, (float*)d_out);
}